// round 13
// baseline (speedup 1.0000x reference)
#include <cuda_runtime.h>
#include <cstdint>

#define BB 2
#define DD 512
#define KK 32
#define NN 4096
#define GRID 128
#define NTHR 1024
#define ZSIZE (BB*DD*KK)

typedef unsigned long long ull;

// ---------- device scratch ----------
__device__ float g_Af[DD*KK];            // s^2
__device__ float g_Bf[DD*KK];            // -2 s^2 c
__device__ float g_C[KK];
__device__ float g_S1part[GRID*KK];
__device__ float g_M2[(size_t)BB*64*DD*KK];  // [b*64+chunk][d][k] 8MB
__device__ float g_SS[BB*64*KK];
__device__ unsigned g_sync[3];

// ---------- f32x2 helpers ----------
__device__ __forceinline__ ull pk2(float lo, float hi) {
    ull r; asm("mov.b64 %0, {%1,%2};" : "=l"(r) : "f"(lo), "f"(hi)); return r;
}
__device__ __forceinline__ void upk2(ull v, float& lo, float& hi) {
    asm("mov.b64 {%0,%1}, %2;" : "=f"(lo), "=f"(hi) : "l"(v));
}
__device__ __forceinline__ ull fma2(ull a, ull b, ull c) {
    ull d; asm("fma.rn.f32x2 %0, %1, %2, %3;" : "=l"(d) : "l"(a), "l"(b), "l"(c)); return d;
}

__device__ __forceinline__ void grid_sync_c(int i) {
    volatile unsigned* ctr = (volatile unsigned*)&g_sync[i];
    __syncthreads();
    if (threadIdx.x == 0) {
        __threadfence();
        atomicAdd(&g_sync[i], 1u);
        while (*ctr < GRID) { __nanosleep(32); }
        __threadfence();
    }
    __syncthreads();
}

// ---------- smem plan (152KB) ----------
// P1: Asf [512][32] 64KB @0 ; Bsf 64KB @65536
// epi alias: Ep [32][512] 64KB @0 (Asf dead) ; Ef [64][32] @131072 ; Qsp @139264 ; red @147456
// P3/P4 alias @0
#define OFF_ASF 0
#define OFF_BSF 65536
#define OFF_EP  0
#define OFF_EF  131072
#define OFF_QS  139264
#define OFF_RED 147456
#define SMEM_TOTAL 155648

__global__ __launch_bounds__(NTHR) void fused_kernel(const float* __restrict__ X,
                                                     const float* __restrict__ cw,
                                                     const float* __restrict__ scale,
                                                     float* __restrict__ out) {
    extern __shared__ unsigned char sm[];
    const int tid  = threadIdx.x;
    const int lane = tid & 31;
    const int w    = tid >> 5;           // 0..31
    const int grp  = w >> 3;             // 0..3 (n-group, 16 n each)
    const int wd   = w & 7;              // d slot
    const int bid  = blockIdx.x;

    // ============ P0: coefficients + C[k] ============
    if (bid == 0 && tid == 0) atomicExch(&g_sync[2], 0u);  // replay-safe pre-reset
    if (tid < 128) {
        int idx = bid*128 + tid;         // d*32+k
        int d = idx >> 5, k = idx & 31;
        float s = scale[idx];
        float c = cw[k*DD + d];
        float s2 = s*s;
        g_Af[idx] = s2;
        g_Bf[idx] = -2.f*s2*c;
    }
    if (bid < KK) {
        float* red = (float*)sm;
        const int k = bid;
        float v = 0.f;
        if (tid < DD) {
            float s = scale[tid*KK + k];
            float c = cw[k*DD + tid];
            v = s*s*c*c;
        }
        red[tid] = v; __syncthreads();
        #pragma unroll
        for (int off = 512; off > 0; off >>= 1) {
            if (tid < off) red[tid] += red[tid + off];
            __syncthreads();
        }
        if (tid == 0) g_C[k] = red[0];
    }
    grid_sync_c(0);

    const int n0 = bid * 64;
    const int b  = n0 >> 12;
    const float* Xbase = X + (size_t)b*DD*NN + (n0 & (NN - 1));

    // ============ P1: E-GEMM — X via uniform LDG, coeffs in smem ============
    ull acc[8];
    {
        float* Asf = (float*)(sm + OFF_ASF);
        float* Bsf = (float*)(sm + OFF_BSF);
        #pragma unroll
        for (int it = 0; it < 4; it++) {
            ((float4*)Asf)[tid + it*1024] = ((const float4*)g_Af)[tid + it*1024];
            ((float4*)Bsf)[tid + it*1024] = ((const float4*)g_Bf)[tid + it*1024];
        }
        __syncthreads();

        const float* Xg = Xbase + grp*16;   // this group's 16 n
        #pragma unroll
        for (int i = 0; i < 8; i++) acc[i] = 0ull;

        #pragma unroll 1
        for (int c = 0; c < 8; c++) {
            const float* Ac = Asf + c*64*KK;
            const float* Bc = Bsf + c*64*KK;
            #pragma unroll
            for (int it = 0; it < 8; it++) {
                int dd = wd + it*8;
                float av = Ac[dd*KK + lane];
                float bv = Bc[dd*KK + lane];
                ull a2 = pk2(av, av), b2 = pk2(bv, bv);
                const longlong2* xr =
                    (const longlong2*)(Xg + (size_t)(c*64 + dd)*NN);
                #pragma unroll
                for (int g = 0; g < 4; g++) {
                    longlong2 xv = __ldg(xr + g);       // uniform LDG.128 (1 line)
                    ull x01 = (ull)xv.x, x23 = (ull)xv.y;
                    ull t0 = fma2(a2, x01, b2);
                    acc[2*g]   = fma2(x01, t0, acc[2*g]);
                    ull t1 = fma2(a2, x23, b2);
                    acc[2*g+1] = fma2(x23, t1, acc[2*g+1]);
                }
            }
        }
        __syncthreads();        // coeff regions dead; Ep aliases them
    }

    // ---- cross-warp E reduce (single wave), softmax, Q out ----
    {
        float* Ep  = (float*)(sm + OFF_EP);      // [32][512]
        float* Ef  = (float*)(sm + OFF_EF);      // [64][32]
        ull*   Qsp = (ull*)(sm + OFF_QS);        // [32 np][32 k]
        float* red = (float*)(sm + OFF_RED);     // [32][33]

        #pragma unroll
        for (int i = 0; i < 8; i++) {
            float lo, hi; upk2(acc[i], lo, hi);
            Ep[w*512 + (2*i  )*KK + lane] = lo;
            Ep[w*512 + (2*i+1)*KK + lane] = hi;
        }
        __syncthreads();
        #pragma unroll
        for (int it = 0; it < 2; it++) {
            int idx = tid + it*1024;             // n*32+k
            int n = idx >> 5, k = idx & 31;
            int gg = n >> 4, nl = n & 15;
            float s = 0.f;
            #pragma unroll
            for (int wdd = 0; wdd < 8; wdd++)
                s += Ep[(gg*8 + wdd)*512 + nl*KK + k];
            Ef[idx] = s;
        }
        __syncthreads();

        float* Qout = out + ZSIZE;
        const float Ck = g_C[lane];
        float qv[2];
        float s1loc = 0.f;
        #pragma unroll
        for (int i = 0; i < 2; i++) {
            int n = w*2 + i;
            float arg = -0.5f * (Ef[n*KK + lane] + Ck);
            float m = arg;
            #pragma unroll
            for (int off = 16; off; off >>= 1) m = fmaxf(m, __shfl_xor_sync(~0u, m, off));
            float ex = __expf(arg - m);
            float ssum = ex;
            #pragma unroll
            for (int off = 16; off; off >>= 1) ssum += __shfl_xor_sync(~0u, ssum, off);
            float q = ex / ssum;
            Qout[(size_t)(n0 + n)*KK + lane] = q;
            qv[i] = q;
            s1loc += q;
        }
        Qsp[w*32 + lane] = pk2(qv[0], qv[1]);
        red[w*33 + lane] = s1loc;
        __syncthreads();
        if (w == 0) {
            float s = 0.f;
            #pragma unroll
            for (int i = 0; i < 32; i++) s += red[i*33 + lane];
            g_S1part[bid*KK + lane] = s;
        }
    }
    __syncthreads();             // Qsp visible to all warps

    // ============ P2': M over 64 n, all 512 d — X via uniform LDG ============
    {
        const ull* Qsp = (const ull*)(sm + OFF_QS);
        const int chunk = bid & 63;
        const int dbase = w*16;

        ull acc2[16];
        #pragma unroll
        for (int i = 0; i < 16; i++) acc2[i] = 0ull;

        #pragma unroll 1
        for (int ng = 0; ng < 4; ng++) {
            ull q2[8];
            #pragma unroll
            for (int j = 0; j < 8; j++)
                q2[j] = Qsp[(ng*8 + j)*32 + lane];
            const float* Xn = Xbase + ng*16;
            #pragma unroll
            for (int dl = 0; dl < 16; dl++) {
                const longlong2* xr =
                    (const longlong2*)(Xn + (size_t)(dbase + dl)*NN);
                longlong2 xa = __ldg(xr + 0);
                longlong2 xb = __ldg(xr + 1);
                longlong2 xc = __ldg(xr + 2);
                longlong2 xd = __ldg(xr + 3);
                ull a = acc2[dl];
                a = fma2(q2[0], (ull)xa.x, a);
                a = fma2(q2[1], (ull)xa.y, a);
                a = fma2(q2[2], (ull)xb.x, a);
                a = fma2(q2[3], (ull)xb.y, a);
                a = fma2(q2[4], (ull)xc.x, a);
                a = fma2(q2[5], (ull)xc.y, a);
                a = fma2(q2[6], (ull)xd.x, a);
                a = fma2(q2[7], (ull)xd.y, a);
                acc2[dl] = a;
            }
        }
        float* dstc = g_M2 + (size_t)(b*64 + chunk)*DD*KK;
        #pragma unroll
        for (int dl = 0; dl < 16; dl++) {
            float lo, hi; upk2(acc2[dl], lo, hi);
            dstc[(dbase + dl)*KK + lane] = lo + hi;
        }
    }
    grid_sync_c(1);
    if (bid == 0 && tid == 0) atomicExch(&g_sync[0], 0u);

    // ============ P3: S1, M reduce, Z, sumsq ============
    const int bf  = bid >> 6;
    const int dtf = bid & 63;
    const int d0f = dtf*8;
    const int dfw = d0f + (w & 7);
    const size_t mi = ((size_t)bf*DD + dfw)*KK + lane;
    {
        float* redM = (float*)sm;            // [32][33]
        float* redS = (float*)(sm + 4224);   // [32][33]
        float* cwf  = (float*)(sm + 8448);   // [32][9]
        float* bsh  = (float*)(sm + 9600);   // [32]
        const int wd8 = w & 7, cg = w >> 3;

        if (tid < 256) {
            int k = tid >> 3, dl = tid & 7;
            cwf[k*9 + dl] = cw[k*DD + d0f + dl];
        }
        float mp = 0.f;
        const float* msrc = g_M2 + (size_t)bf*64*DD*KK + (size_t)dfw*KK + lane;
        #pragma unroll
        for (int j = 0; j < 16; j++)
            mp += msrc[(size_t)(cg*16 + j)*DD*KK];
        redM[w*33 + lane] = mp;

        float s1p = g_S1part[(bf*64 + w)*KK + lane]
                  + g_S1part[(bf*64 + 32 + w)*KK + lane];
        redS[w*33 + lane] = s1p;
        __syncthreads();
        if (w == 0) {
            float s = 0.f;
            #pragma unroll
            for (int i = 0; i < 32; i++) s += redS[i*33 + lane];
            bsh[lane] = 1.f / s;
        }
        __syncthreads();
        float z = 0.f;
        if (w < 8) {
            float m = redM[w*33 + lane] + redM[(8+w)*33 + lane]
                    + redM[(16+w)*33 + lane] + redM[(24+w)*33 + lane];
            z = scale[dfw*KK + lane] * (m*bsh[lane] - cwf[lane*9 + (w & 7)]);
            out[mi] = z;
        }
        __syncthreads();
        if (w < 8) redM[w*33 + lane] = z*z;
        __syncthreads();
        if (w == 0) {
            float s = 0.f;
            #pragma unroll
            for (int i = 0; i < 8; i++) s += redM[i*33 + lane];
            g_SS[(bf*64 + dtf)*KK + lane] = s;
        }
    }
    grid_sync_c(2);
    if (bid == 0 && tid == 0) atomicExch(&g_sync[1], 0u);

    // ============ P4: rescale ============
    {
        float* red = (float*)sm;
        float* bsh = (float*)(sm + 9600);
        float ssp = g_SS[(bf*64 + w)*KK + lane]
                  + g_SS[(bf*64 + 32 + w)*KK + lane];
        red[w*33 + lane] = ssp;
        __syncthreads();
        if (w == 0) {
            float s = 0.f;
            #pragma unroll
            for (int i = 0; i < 32; i++) s += red[i*33 + lane];
            bsh[lane] = rsqrtf(s);
        }
        __syncthreads();
        if (w < 8) out[mi] *= bsh[lane];
    }
}

extern "C" void kernel_launch(void* const* d_in, const int* in_sizes, int n_in,
                              void* d_out, int out_size) {
    const float* X     = (const float*)d_in[0];
    const float* cw    = (const float*)d_in[1];
    const float* scale = (const float*)d_in[2];
    float* out = (float*)d_out;

    cudaFuncSetAttribute(fused_kernel, cudaFuncAttributeMaxDynamicSharedMemorySize,
                         SMEM_TOTAL);
    fused_kernel<<<GRID, NTHR, SMEM_TOTAL>>>(X, cw, scale, out);
}

// round 14
// speedup vs baseline: 1.3349x; 1.3349x over previous
#include <cuda_runtime.h>
#include <cstdint>

#define BB 2
#define DD 512
#define KK 32
#define NN 4096
#define GRID 128
#define NTHR 1024
#define ZSIZE (BB*DD*KK)

typedef unsigned long long ull;

// ---------- device scratch ----------
__device__ float2 g_ABi[DD*KK];          // (s^2, -2 s^2 c) interleaved
__device__ float g_C[KK];
__device__ float g_S1part[GRID*KK];
__device__ float g_M2[(size_t)BB*64*DD*KK];  // [b*64+chunk][d][k] 8MB
__device__ float g_SS[BB*64*KK];
__device__ unsigned g_sync[3];

// ---------- f32x2 helpers ----------
__device__ __forceinline__ ull pk2(float lo, float hi) {
    ull r; asm("mov.b64 %0, {%1,%2};" : "=l"(r) : "f"(lo), "f"(hi)); return r;
}
__device__ __forceinline__ void upk2(ull v, float& lo, float& hi) {
    asm("mov.b64 {%0,%1}, %2;" : "=f"(lo), "=f"(hi) : "l"(v));
}
__device__ __forceinline__ ull fma2(ull a, ull b, ull c) {
    ull d; asm("fma.rn.f32x2 %0, %1, %2, %3;" : "=l"(d) : "l"(a), "l"(b), "l"(c)); return d;
}

__device__ __forceinline__ void grid_sync_c(int i) {
    volatile unsigned* ctr = (volatile unsigned*)&g_sync[i];
    __syncthreads();
    if (threadIdx.x == 0) {
        __threadfence();
        atomicAdd(&g_sync[i], 1u);
        while (*ctr < GRID) { __nanosleep(32); }
        __threadfence();
    }
    __syncthreads();
}

// ---------- smem plan (212KB) ----------
// Xs [512][64] f32 @0 : 128KB (LIVE through P1 epilogue AND P2)
// AB0 float2[128][32] @131072 : 32KB ; AB1 @163840 : 32KB
// epilogue alias: Ep [32][512] @131072 (64KB, AB dead)
// Ef [64][32] @196608 ; Qsp ull[32][32] @204800 ; red [32][33] @212992
// P3/P4 alias @0 (Xs dead)
#define OFF_AB0 131072
#define OFF_AB1 163840
#define OFF_EP  131072
#define OFF_EF  196608
#define OFF_QS  204800
#define OFF_RED 212992
#define SMEM_TOTAL 217216

__global__ __launch_bounds__(NTHR) void fused_kernel(const float* __restrict__ X,
                                                     const float* __restrict__ cw,
                                                     const float* __restrict__ scale,
                                                     float* __restrict__ out) {
    extern __shared__ unsigned char sm[];
    const int tid  = threadIdx.x;
    const int lane = tid & 31;
    const int w    = tid >> 5;           // 0..31
    const int grp  = w >> 3;             // 0..3 (n-group, 16 n)
    const int wd   = w & 7;              // d slot
    const int bid  = blockIdx.x;

    uint32_t smem_u32;
    asm("{ .reg .u64 t; cvta.to.shared.u64 t, %1; cvt.u32.u64 %0, t; }"
        : "=r"(smem_u32) : "l"(sm));

    // ============ P0: coefficients + C[k] ============
    if (bid == 0 && tid == 0) atomicExch(&g_sync[2], 0u);  // replay-safe pre-reset
    if (tid < 128) {
        int idx = bid*128 + tid;         // d*32+k
        int d = idx >> 5, k = idx & 31;
        float s = scale[idx];
        float c = cw[k*DD + d];
        float s2 = s*s;
        g_ABi[idx] = make_float2(s2, -2.f*s2*c);
    }
    if (bid < KK) {
        float* red = (float*)sm;
        const int k = bid;
        float v = 0.f;
        if (tid < DD) {
            float s = scale[tid*KK + k];
            float c = cw[k*DD + tid];
            v = s*s*c*c;
        }
        red[tid] = v; __syncthreads();
        #pragma unroll
        for (int off = 512; off > 0; off >>= 1) {
            if (tid < off) red[tid] += red[tid + off];
            __syncthreads();
        }
        if (tid == 0) g_C[k] = red[0];
    }
    grid_sync_c(0);

    const int n0 = bid * 64;
    const int b  = n0 >> 12;
    const float* Xb = X + (size_t)b*DD*NN + (n0 & (NN - 1));
    float* Xs = (float*)sm;              // [512][64]

    // ============ P1: E-GEMM ============
    ull acc[8];
    {
        // stage FULL X tile once + AB superchunk 0, all via cp.async
        #pragma unroll
        for (int it = 0; it < 8; it++) {
            int idx = tid + it*1024;     // 0..8191 float4
            int row = idx >> 4, c4 = idx & 15;
            uint32_t dst = smem_u32 + (uint32_t)(row*64 + c4*4)*4u;
            const float* src = Xb + (size_t)row*NN + c4*4;
            asm volatile("cp.async.ca.shared.global [%0], [%1], 16;" :: "r"(dst), "l"(src));
        }
        #pragma unroll
        for (int it = 0; it < 2; it++) {
            int idx = tid + it*1024;     // 0..2047 float4 (32KB)
            uint32_t dst = smem_u32 + OFF_AB0 + (uint32_t)idx*16u;
            const char* src = (const char*)g_ABi + idx*16;
            asm volatile("cp.async.ca.shared.global [%0], [%1], 16;" :: "r"(dst), "l"(src));
        }
        asm volatile("cp.async.commit_group;");

        #pragma unroll
        for (int i = 0; i < 8; i++) acc[i] = 0ull;

        #pragma unroll 1
        for (int sc = 0; sc < 4; sc++) {     // 4 superchunks of 128 d
            asm volatile("cp.async.wait_group 0;");
            __syncthreads();
            if (sc < 3) {                    // stage next AB superchunk
                uint32_t base = ((sc + 1) & 1) ? OFF_AB1 : OFF_AB0;
                #pragma unroll
                for (int it = 0; it < 2; it++) {
                    int idx = tid + it*1024;
                    uint32_t dst = smem_u32 + base + (uint32_t)idx*16u;
                    const char* src = (const char*)(g_ABi + (sc+1)*4096) + idx*16;
                    asm volatile("cp.async.ca.shared.global [%0], [%1], 16;" :: "r"(dst), "l"(src));
                }
                asm volatile("cp.async.commit_group;");
            }
            const float2* ABc = (const float2*)(sm + ((sc & 1) ? OFF_AB1 : OFF_AB0));
            #pragma unroll
            for (int it = 0; it < 16; it++) {
                int dl = wd + it*8;          // 0..127 within superchunk
                float2 ab = ABc[dl*KK + lane];
                ull a2 = pk2(ab.x, ab.x), b2 = pk2(ab.y, ab.y);
                const float* xr = &Xs[(sc*128 + dl)*64 + grp*16];
                #pragma unroll
                for (int g = 0; g < 4; g++) {
                    longlong2 xv = *reinterpret_cast<const longlong2*>(xr + g*4);
                    ull x01 = (ull)xv.x, x23 = (ull)xv.y;
                    ull t0 = fma2(a2, x01, b2);
                    acc[2*g]   = fma2(x01, t0, acc[2*g]);
                    ull t1 = fma2(a2, x23, b2);
                    acc[2*g+1] = fma2(x23, t1, acc[2*g+1]);
                }
            }
        }
        __syncthreads();        // AB buffers dead; Ep may alias them
    }

    // ---- cross-warp E reduce (single wave), softmax, Q out ----
    {
        float* Ep  = (float*)(sm + OFF_EP);      // [32][512]
        float* Ef  = (float*)(sm + OFF_EF);      // [64][32]
        ull*   Qsp = (ull*)(sm + OFF_QS);        // [32 np][32 k]
        float* red = (float*)(sm + OFF_RED);     // [32][33]

        #pragma unroll
        for (int i = 0; i < 8; i++) {
            float lo, hi; upk2(acc[i], lo, hi);
            Ep[w*512 + (2*i  )*KK + lane] = lo;
            Ep[w*512 + (2*i+1)*KK + lane] = hi;
        }
        __syncthreads();
        #pragma unroll
        for (int it = 0; it < 2; it++) {
            int idx = tid + it*1024;             // n*32+k
            int n = idx >> 5, k = idx & 31;
            int gg = n >> 4, nl = n & 15;
            float s = 0.f;
            #pragma unroll
            for (int wdd = 0; wdd < 8; wdd++)
                s += Ep[(gg*8 + wdd)*512 + nl*KK + k];
            Ef[idx] = s;
        }
        __syncthreads();

        float* Qout = out + ZSIZE;
        const float Ck = g_C[lane];
        float qv[2];
        float s1loc = 0.f;
        #pragma unroll
        for (int i = 0; i < 2; i++) {
            int n = w*2 + i;
            float arg = -0.5f * (Ef[n*KK + lane] + Ck);
            float m = arg;
            #pragma unroll
            for (int off = 16; off; off >>= 1) m = fmaxf(m, __shfl_xor_sync(~0u, m, off));
            float ex = __expf(arg - m);
            float ssum = ex;
            #pragma unroll
            for (int off = 16; off; off >>= 1) ssum += __shfl_xor_sync(~0u, ssum, off);
            float q = ex / ssum;
            Qout[(size_t)(n0 + n)*KK + lane] = q;
            qv[i] = q;
            s1loc += q;
        }
        Qsp[w*32 + lane] = pk2(qv[0], qv[1]);
        red[w*33 + lane] = s1loc;
        __syncthreads();
        if (w == 0) {
            float s = 0.f;
            #pragma unroll
            for (int i = 0; i < 32; i++) s += red[i*33 + lane];
            g_S1part[bid*KK + lane] = s;
        }
    }
    __syncthreads();             // Qsp visible to all warps; Xs still live

    // ============ P2': M over 64 n, all 512 d — reuses Xs + Qsp ============
    {
        const ull* Qsp = (const ull*)(sm + OFF_QS);
        const int chunk = bid & 63;
        const int dbase = w*16;

        ull acc2[16];
        #pragma unroll
        for (int i = 0; i < 16; i++) acc2[i] = 0ull;

        #pragma unroll 1
        for (int ng = 0; ng < 4; ng++) {
            ull q2[8];
            #pragma unroll
            for (int j = 0; j < 8; j++)
                q2[j] = Qsp[(ng*8 + j)*32 + lane];
            #pragma unroll
            for (int dl = 0; dl < 16; dl++) {
                const float* xr = &Xs[(dbase + dl)*64 + ng*16];
                longlong2 xa = *(const longlong2*)(xr);
                longlong2 xb = *(const longlong2*)(xr + 4);
                longlong2 xc = *(const longlong2*)(xr + 8);
                longlong2 xd = *(const longlong2*)(xr + 12);
                ull a = acc2[dl];
                a = fma2(q2[0], (ull)xa.x, a);
                a = fma2(q2[1], (ull)xa.y, a);
                a = fma2(q2[2], (ull)xb.x, a);
                a = fma2(q2[3], (ull)xb.y, a);
                a = fma2(q2[4], (ull)xc.x, a);
                a = fma2(q2[5], (ull)xc.y, a);
                a = fma2(q2[6], (ull)xd.x, a);
                a = fma2(q2[7], (ull)xd.y, a);
                acc2[dl] = a;
            }
        }
        float* dstc = g_M2 + (size_t)(b*64 + chunk)*DD*KK;
        #pragma unroll
        for (int dl = 0; dl < 16; dl++) {
            float lo, hi; upk2(acc2[dl], lo, hi);
            dstc[(dbase + dl)*KK + lane] = lo + hi;
        }
    }
    grid_sync_c(1);
    if (bid == 0 && tid == 0) atomicExch(&g_sync[0], 0u);

    // ============ P3: S1, M reduce, Z, sumsq ============
    const int bf  = bid >> 6;
    const int dtf = bid & 63;
    const int d0f = dtf*8;
    const int dfw = d0f + (w & 7);
    const size_t mi = ((size_t)bf*DD + dfw)*KK + lane;
    {
        float* redM = (float*)sm;            // [32][33]
        float* redS = (float*)(sm + 4224);   // [32][33]
        float* cwf  = (float*)(sm + 8448);   // [32][9]
        float* bsh  = (float*)(sm + 9600);   // [32]
        const int wd8 = w & 7, cg = w >> 3;

        if (tid < 256) {
            int k = tid >> 3, dl = tid & 7;
            cwf[k*9 + dl] = cw[k*DD + d0f + dl];
        }
        float mp = 0.f;
        const float* msrc = g_M2 + (size_t)bf*64*DD*KK + (size_t)dfw*KK + lane;
        #pragma unroll
        for (int j = 0; j < 16; j++)
            mp += msrc[(size_t)(cg*16 + j)*DD*KK];
        redM[w*33 + lane] = mp;

        float s1p = g_S1part[(bf*64 + w)*KK + lane]
                  + g_S1part[(bf*64 + 32 + w)*KK + lane];
        redS[w*33 + lane] = s1p;
        __syncthreads();
        if (w == 0) {
            float s = 0.f;
            #pragma unroll
            for (int i = 0; i < 32; i++) s += redS[i*33 + lane];
            bsh[lane] = 1.f / s;
        }
        __syncthreads();
        float z = 0.f;
        if (w < 8) {
            float m = redM[w*33 + lane] + redM[(8+w)*33 + lane]
                    + redM[(16+w)*33 + lane] + redM[(24+w)*33 + lane];
            z = scale[dfw*KK + lane] * (m*bsh[lane] - cwf[lane*9 + (w & 7)]);
            out[mi] = z;
        }
        __syncthreads();
        if (w < 8) redM[w*33 + lane] = z*z;
        __syncthreads();
        if (w == 0) {
            float s = 0.f;
            #pragma unroll
            for (int i = 0; i < 8; i++) s += redM[i*33 + lane];
            g_SS[(bf*64 + dtf)*KK + lane] = s;
        }
    }
    grid_sync_c(2);
    if (bid == 0 && tid == 0) atomicExch(&g_sync[1], 0u);

    // ============ P4: rescale ============
    {
        float* red = (float*)sm;
        float* bsh = (float*)(sm + 9600);
        float ssp = g_SS[(bf*64 + w)*KK + lane]
                  + g_SS[(bf*64 + 32 + w)*KK + lane];
        red[w*33 + lane] = ssp;
        __syncthreads();
        if (w == 0) {
            float s = 0.f;
            #pragma unroll
            for (int i = 0; i < 32; i++) s += red[i*33 + lane];
            bsh[lane] = rsqrtf(s);
        }
        __syncthreads();
        if (w < 8) out[mi] *= bsh[lane];
    }
}

extern "C" void kernel_launch(void* const* d_in, const int* in_sizes, int n_in,
                              void* d_out, int out_size) {
    const float* X     = (const float*)d_in[0];
    const float* cw    = (const float*)d_in[1];
    const float* scale = (const float*)d_in[2];
    float* out = (float*)d_out;

    cudaFuncSetAttribute(fused_kernel, cudaFuncAttributeMaxDynamicSharedMemorySize,
                         SMEM_TOTAL);
    fused_kernel<<<GRID, NTHR, SMEM_TOTAL>>>(X, cw, scale, out);
}